// round 2
// baseline (speedup 1.0000x reference)
#include <cuda_runtime.h>

// ---------------------------------------------------------------------------
// VAE_CDDD_decoder: 3-layer GRU decoder, B=1024, S=350, VOCAB=41
// Strategy (round 1):
//   * Precompute G = (W_emb.T + b_emb) @ Wih0.T + bih0  (41 x 768 table)
//     -> layer-0 input GEMM becomes a tiny gather.
//   * Precompute transposed weights (k-major) for coalesced L2 streaming.
//   * Precompute initial hidden state: latent @ W_init.T + b_init.
//   * Main persistent kernel: 128 blocks x 8 batch rows, 350 steps, all
//     state in SMEM ([unit][row] layout -> broadcast LDS.128).
//   * fp32 math via packed fma.rn.f32x2 (rows packed in pairs) to hit
//     128 FMA/cyc/SM on sm_103a.
// ---------------------------------------------------------------------------

#define BB      1024
#define SS      350
#define VV      41
#define EE      512
#define H1      256
#define H2      128
#define H3      32
#define INITD   416      // 256+128+32
#define SOS_TOK 1
#define G3      768      // 3*H1
#define ROWS    8
#define NBLK    128
#define NTHR    256

typedef unsigned long long ull;

// ------------------------- device scratch (no allocs) ----------------------
__device__ float g_WhhT0[H1 * G3];       // [256][768]
__device__ float g_WihT0[EE * G3];       // [512][768]
__device__ float g_WihT1[H1 * 384];      // [256][384]
__device__ float g_WhhT1[H2 * 384];      // [128][384]
__device__ float g_WihT2[H2 * 96];       // [128][96]
__device__ float g_WhhT2[H3 * 96];       // [32][96]
__device__ float g_WprojT[H3 * VV];      // [32][41]
__device__ float g_WinitT[EE * INITD];   // [512][416]
__device__ float g_G[VV * G3];           // [41][768]
__device__ float g_hinit[BB * INITD];

// ------------------------- packed f32x2 helpers ----------------------------
__device__ __forceinline__ ull splat2(float w) {
    ull r;
    asm("mov.b64 %0, {%1, %1};" : "=l"(r) : "f"(w));
    return r;
}
__device__ __forceinline__ void fma2(ull& acc, ull a, ull b) {
    asm("fma.rn.f32x2 %0, %1, %2, %0;" : "+l"(acc) : "l"(a), "l"(b));
}
__device__ __forceinline__ float2 unpack2(ull v) {
    float2 f;
    asm("mov.b64 {%0, %1}, %2;" : "=f"(f.x), "=f"(f.y) : "l"(v));
    return f;
}
__device__ __forceinline__ float sigm(float x) { return 1.0f / (1.0f + expf(-x)); }

// ------------------------- precompute kernels ------------------------------
__global__ void k_transpose(const float* __restrict__ in, int R, int C, int which) {
    float* out;
    switch (which) {
        case 0: out = g_WhhT0;  break;
        case 1: out = g_WihT0;  break;
        case 2: out = g_WihT1;  break;
        case 3: out = g_WhhT1;  break;
        case 4: out = g_WihT2;  break;
        case 5: out = g_WhhT2;  break;
        case 6: out = g_WprojT; break;
        default: out = g_WinitT; break;
    }
    int idx = blockIdx.x * blockDim.x + threadIdx.x;
    if (idx < R * C) {
        int r = idx / C, c = idx - r * C;
        out[c * R + r] = in[idx];
    }
}

// G[v][f] = bih0[f] + sum_e (W_emb[e][v] + b_emb[e]) * Wih0[f][e]
__global__ void k_build_G(const float* __restrict__ W_emb,
                          const float* __restrict__ b_emb,
                          const float* __restrict__ bih0) {
    __shared__ float emb[EE];
    int v = blockIdx.x;
    for (int e = threadIdx.x; e < EE; e += blockDim.x)
        emb[e] = W_emb[e * VV + v] + b_emb[e];
    __syncthreads();
    for (int f = threadIdx.x; f < G3; f += blockDim.x) {
        float acc = bih0[f];
        for (int e = 0; e < EE; e++)
            acc += emb[e] * g_WihT0[e * G3 + f];
        g_G[v * G3 + f] = acc;
    }
}

// hinit[b][j] = b_init[j] + sum_k latent[b][k] * W_init[j][k]
__global__ void k_hinit(const float* __restrict__ latent,
                        const float* __restrict__ b_init) {
    __shared__ float lat[EE];
    int b = blockIdx.x;
    for (int k = threadIdx.x; k < EE; k += blockDim.x)
        lat[k] = latent[b * EE + k];
    __syncthreads();
    for (int j = threadIdx.x; j < INITD; j += blockDim.x) {
        float acc = b_init[j];
        for (int k = 0; k < EE; k++)
            acc += lat[k] * g_WinitT[k * INITD + j];
        g_hinit[b * INITD + j] = acc;
    }
}

// ------------------------- main persistent kernel --------------------------
__global__ __launch_bounds__(NTHR) void k_main(
    const int*   __restrict__ target,
    const float* __restrict__ bhh0,
    const float* __restrict__ bih1, const float* __restrict__ bhh1,
    const float* __restrict__ bih2, const float* __restrict__ bhh2,
    const float* __restrict__ bproj,
    float* __restrict__ out, float* __restrict__ pred, int write_pred)
{
    const int t    = threadIdx.x;
    const int row0 = blockIdx.x * ROWS;

    __shared__ __align__(16) float h0s[H1][ROWS];   // [unit][row]
    __shared__ __align__(16) float h1s[H2][ROWS];
    __shared__ __align__(16) float h2s[H3][ROWS];
    __shared__ unsigned char stok[SS][ROWS];
    __shared__ float slog[VV][ROWS];

    // ---- init hidden states from precomputed hinit ----
    #pragma unroll
    for (int r = 0; r < ROWS; r++)
        h0s[t][r] = g_hinit[(row0 + r) * INITD + t];
    if (t < H2) {
        #pragma unroll
        for (int r = 0; r < ROWS; r++)
            h1s[t][r] = g_hinit[(row0 + r) * INITD + 256 + t];
    }
    if (t < H3) {
        #pragma unroll
        for (int r = 0; r < ROWS; r++)
            h2s[t][r] = g_hinit[(row0 + r) * INITD + 384 + t];
    }
    // ---- tokens (teacher forcing, shifted; tok[0] = SOS) ----
    for (int idx = t; idx < SS * ROWS; idx += NTHR) {
        int s = idx >> 3, r = idx & 7;
        int tk = (s == 0) ? SOS_TOK : target[(row0 + r) * SS + s];
        stok[s][r] = (unsigned char)tk;
    }

    // ---- per-thread bias registers ----
    const float b0r = bhh0[t], b0z = bhh0[t + 256], b0n = bhh0[t + 512];
    const int   u1  = t & 127, rb1 = (t >> 7) * 4;
    const float b1r = bih1[u1] + bhh1[u1];
    const float b1z = bih1[u1 + 128] + bhh1[u1 + 128];
    const float b1i = bih1[u1 + 256];
    const float b1h = bhh1[u1 + 256];
    int u2 = 0, rb2 = 0;
    float b2r = 0.f, b2z = 0.f, b2i = 0.f, b2h = 0.f;
    if (t < 64) {
        u2 = t & 31; rb2 = (t >> 5) * 4;
        b2r = bih2[u2] + bhh2[u2];
        b2z = bih2[u2 + 32] + bhh2[u2 + 32];
        b2i = bih2[u2 + 64];
        b2h = bhh2[u2 + 64];
    }
    __syncthreads();

    for (int step = 0; step < SS; ++step) {
        // ---------------- layer 0: gi gather from G table ----------------
        float gir[8], giz[8], gin[8];
        #pragma unroll
        for (int r = 0; r < ROWS; r++) {
            int base = ((int)stok[step][r]) * G3 + t;
            gir[r] = __ldg(&g_G[base]);
            giz[r] = __ldg(&g_G[base + 256]);
            gin[r] = __ldg(&g_G[base + 512]);
        }
        // ---------------- layer 0: gh = h0 @ Whh0.T ----------------------
        ull ar[4], az[4], an[4];
        #pragma unroll
        for (int p = 0; p < 4; p++) { ar[p] = splat2(b0r); az[p] = splat2(b0z); an[p] = splat2(b0n); }
        for (int k = 0; k < H1; k += 4) {
            #pragma unroll
            for (int kk = 0; kk < 4; kk++) {
                const int ki = k + kk;
                float wr = __ldg(&g_WhhT0[ki * G3 + t]);
                float wz = __ldg(&g_WhhT0[ki * G3 + t + 256]);
                float wn = __ldg(&g_WhhT0[ki * G3 + t + 512]);
                ull wr2 = splat2(wr), wz2 = splat2(wz), wn2 = splat2(wn);
                const ulonglong2* hp = (const ulonglong2*)&h0s[ki][0];
                ulonglong2 hA = hp[0], hB = hp[1];
                fma2(ar[0], wr2, hA.x); fma2(ar[1], wr2, hA.y);
                fma2(ar[2], wr2, hB.x); fma2(ar[3], wr2, hB.y);
                fma2(az[0], wz2, hA.x); fma2(az[1], wz2, hA.y);
                fma2(az[2], wz2, hB.x); fma2(az[3], wz2, hB.y);
                fma2(an[0], wn2, hA.x); fma2(an[1], wn2, hA.y);
                fma2(an[2], wn2, hB.x); fma2(an[3], wn2, hB.y);
            }
        }
        // ---------------- layer 0: pointwise (unit = t) -------------------
        float h0new[8];
        #pragma unroll
        for (int p = 0; p < 4; p++) {
            float2 fr = unpack2(ar[p]), fz = unpack2(az[p]), fn = unpack2(an[p]);
            int i0 = 2 * p, i1 = 2 * p + 1;
            float rg = sigm(gir[i0] + fr.x);
            float zg = sigm(giz[i0] + fz.x);
            float ng = tanhf(gin[i0] + rg * fn.x);
            h0new[i0] = (1.0f - zg) * ng + zg * h0s[t][i0];
            rg = sigm(gir[i1] + fr.y);
            zg = sigm(giz[i1] + fz.y);
            ng = tanhf(gin[i1] + rg * fn.y);
            h0new[i1] = (1.0f - zg) * ng + zg * h0s[t][i1];
        }
        __syncthreads();
        *(float4*)&h0s[t][0] = make_float4(h0new[0], h0new[1], h0new[2], h0new[3]);
        *(float4*)&h0s[t][4] = make_float4(h0new[4], h0new[5], h0new[6], h0new[7]);
        __syncthreads();

        // ---------------- layer 1 (unit u1, rows rb1..rb1+3) --------------
        ull a1r[2], a1z[2], a1i[2], a1h[2];
        a1r[0] = a1r[1] = splat2(b1r);
        a1z[0] = a1z[1] = splat2(b1z);
        a1i[0] = a1i[1] = splat2(b1i);
        a1h[0] = a1h[1] = splat2(b1h);
        for (int k = 0; k < H1; k += 4) {           // gi side: x = h0_new
            #pragma unroll
            for (int kk = 0; kk < 4; kk++) {
                const int ki = k + kk;
                float wr = __ldg(&g_WihT1[ki * 384 + u1]);
                float wz = __ldg(&g_WihT1[ki * 384 + u1 + 128]);
                float wn = __ldg(&g_WihT1[ki * 384 + u1 + 256]);
                ulonglong2 hA = *(const ulonglong2*)&h0s[ki][rb1];
                ull wr2 = splat2(wr), wz2 = splat2(wz), wn2 = splat2(wn);
                fma2(a1r[0], wr2, hA.x); fma2(a1r[1], wr2, hA.y);
                fma2(a1z[0], wz2, hA.x); fma2(a1z[1], wz2, hA.y);
                fma2(a1i[0], wn2, hA.x); fma2(a1i[1], wn2, hA.y);
            }
        }
        for (int k = 0; k < H2; k += 4) {           // gh side: h1
            #pragma unroll
            for (int kk = 0; kk < 4; kk++) {
                const int ki = k + kk;
                float wr = __ldg(&g_WhhT1[ki * 384 + u1]);
                float wz = __ldg(&g_WhhT1[ki * 384 + u1 + 128]);
                float wn = __ldg(&g_WhhT1[ki * 384 + u1 + 256]);
                ulonglong2 hA = *(const ulonglong2*)&h1s[ki][rb1];
                ull wr2 = splat2(wr), wz2 = splat2(wz), wn2 = splat2(wn);
                fma2(a1r[0], wr2, hA.x); fma2(a1r[1], wr2, hA.y);
                fma2(a1z[0], wz2, hA.x); fma2(a1z[1], wz2, hA.y);
                fma2(a1h[0], wn2, hA.x); fma2(a1h[1], wn2, hA.y);
            }
        }
        float h1new[4];
        #pragma unroll
        for (int p = 0; p < 2; p++) {
            float2 fr = unpack2(a1r[p]), fz = unpack2(a1z[p]);
            float2 fi = unpack2(a1i[p]), fh = unpack2(a1h[p]);
            int j0 = 2 * p, j1 = 2 * p + 1;
            float rg = sigm(fr.x), zg = sigm(fz.x);
            float ng = tanhf(fi.x + rg * fh.x);
            h1new[j0] = (1.0f - zg) * ng + zg * h1s[u1][rb1 + j0];
            rg = sigm(fr.y); zg = sigm(fz.y);
            ng = tanhf(fi.y + rg * fh.y);
            h1new[j1] = (1.0f - zg) * ng + zg * h1s[u1][rb1 + j1];
        }
        __syncthreads();
        *(float4*)&h1s[u1][rb1] = make_float4(h1new[0], h1new[1], h1new[2], h1new[3]);
        __syncthreads();

        // ---------------- layer 2 (threads < 64) --------------------------
        ull a2r[2], a2z[2], a2i[2], a2h[2];
        float h2new[4];
        if (t < 64) {
            a2r[0] = a2r[1] = splat2(b2r);
            a2z[0] = a2z[1] = splat2(b2z);
            a2i[0] = a2i[1] = splat2(b2i);
            a2h[0] = a2h[1] = splat2(b2h);
            for (int k = 0; k < H2; k += 4) {       // gi side: x = h1_new
                #pragma unroll
                for (int kk = 0; kk < 4; kk++) {
                    const int ki = k + kk;
                    float wr = __ldg(&g_WihT2[ki * 96 + u2]);
                    float wz = __ldg(&g_WihT2[ki * 96 + u2 + 32]);
                    float wn = __ldg(&g_WihT2[ki * 96 + u2 + 64]);
                    ulonglong2 hA = *(const ulonglong2*)&h1s[ki][rb2];
                    ull wr2 = splat2(wr), wz2 = splat2(wz), wn2 = splat2(wn);
                    fma2(a2r[0], wr2, hA.x); fma2(a2r[1], wr2, hA.y);
                    fma2(a2z[0], wz2, hA.x); fma2(a2z[1], wz2, hA.y);
                    fma2(a2i[0], wn2, hA.x); fma2(a2i[1], wn2, hA.y);
                }
            }
            for (int k = 0; k < H3; k += 4) {       // gh side: h2
                #pragma unroll
                for (int kk = 0; kk < 4; kk++) {
                    const int ki = k + kk;
                    float wr = __ldg(&g_WhhT2[ki * 96 + u2]);
                    float wz = __ldg(&g_WhhT2[ki * 96 + u2 + 32]);
                    float wn = __ldg(&g_WhhT2[ki * 96 + u2 + 64]);
                    ulonglong2 hA = *(const ulonglong2*)&h2s[ki][rb2];
                    ull wr2 = splat2(wr), wz2 = splat2(wz), wn2 = splat2(wn);
                    fma2(a2r[0], wr2, hA.x); fma2(a2r[1], wr2, hA.y);
                    fma2(a2z[0], wz2, hA.x); fma2(a2z[1], wz2, hA.y);
                    fma2(a2h[0], wn2, hA.x); fma2(a2h[1], wn2, hA.y);
                }
            }
            #pragma unroll
            for (int p = 0; p < 2; p++) {
                float2 fr = unpack2(a2r[p]), fz = unpack2(a2z[p]);
                float2 fi = unpack2(a2i[p]), fh = unpack2(a2h[p]);
                int j0 = 2 * p, j1 = 2 * p + 1;
                float rg = sigm(fr.x), zg = sigm(fz.x);
                float ng = tanhf(fi.x + rg * fh.x);
                h2new[j0] = (1.0f - zg) * ng + zg * h2s[u2][rb2 + j0];
                rg = sigm(fr.y); zg = sigm(fz.y);
                ng = tanhf(fi.y + rg * fh.y);
                h2new[j1] = (1.0f - zg) * ng + zg * h2s[u2][rb2 + j1];
            }
        }
        __syncthreads();
        if (t < 64)
            *(float4*)&h2s[u2][rb2] = make_float4(h2new[0], h2new[1], h2new[2], h2new[3]);
        __syncthreads();

        // ---------------- projection + output + argmax --------------------
        for (int idx = t; idx < VV * ROWS; idx += NTHR) {
            int r = idx / VV, v = idx - r * VV;
            float acc = bproj[v];
            #pragma unroll
            for (int k = 0; k < H3; k++)
                acc += h2s[k][r] * __ldg(&g_WprojT[k * VV + v]);
            out[(size_t)(row0 + r) * (SS * VV) + (size_t)step * VV + v] = acc;
            slog[v][r] = acc;
        }
        __syncthreads();
        if (t < ROWS && write_pred) {
            float best = slog[0][t];
            int bi = 0;
            #pragma unroll
            for (int v = 1; v < VV; v++) {
                float x = slog[v][t];
                if (x > best) { best = x; bi = v; }
            }
            pred[(size_t)(row0 + t) * SS + step] = (float)bi;
        }
        __syncthreads();
    }
}

// ------------------------- launch ------------------------------------------
extern "C" void kernel_launch(void* const* d_in, const int* in_sizes, int n_in,
                              void* d_out, int out_size) {
    const float* latent  = (const float*)d_in[0];
    const int*   target  = (const int*)  d_in[1];
    const float* W_emb   = (const float*)d_in[2];
    const float* b_emb   = (const float*)d_in[3];
    const float* W_init  = (const float*)d_in[4];
    const float* b_init  = (const float*)d_in[5];
    const float* Wih0    = (const float*)d_in[6];
    const float* Whh0    = (const float*)d_in[7];
    const float* bih0    = (const float*)d_in[8];
    const float* bhh0    = (const float*)d_in[9];
    const float* Wih1    = (const float*)d_in[10];
    const float* Whh1    = (const float*)d_in[11];
    const float* bih1    = (const float*)d_in[12];
    const float* bhh1    = (const float*)d_in[13];
    const float* Wih2    = (const float*)d_in[14];
    const float* Whh2    = (const float*)d_in[15];
    const float* bih2    = (const float*)d_in[16];
    const float* bhh2    = (const float*)d_in[17];
    const float* W_proj  = (const float*)d_in[18];
    const float* b_proj  = (const float*)d_in[19];

    (void)in_sizes; (void)n_in;

    // transposed weights (k-major) for coalesced streaming
    {
        struct { const float* p; int R, C, w; } ts[8] = {
            { Whh0,   G3,  H1,   0 },
            { Wih0,   G3,  EE,   1 },
            { Wih1,   384, H1,   2 },
            { Whh1,   384, H2,   3 },
            { Wih2,   96,  H2,   4 },
            { Whh2,   96,  H3,   5 },
            { W_proj, VV,  H3,   6 },
            { W_init, INITD, EE, 7 },
        };
        for (int i = 0; i < 8; i++) {
            int n = ts[i].R * ts[i].C;
            k_transpose<<<(n + 255) / 256, 256>>>(ts[i].p, ts[i].R, ts[i].C, ts[i].w);
        }
    }
    k_build_G<<<VV, 256>>>(W_emb, b_emb, bih0);
    k_hinit<<<BB, 256>>>(latent, b_init);

    float* out  = (float*)d_out;
    float* pred = out + (size_t)BB * SS * VV;
    int wp = (out_size >= (int)((size_t)BB * SS * VV + (size_t)BB * SS)) ? 1 : 0;

    k_main<<<NBLK, NTHR>>>(target, bhh0, bih1, bhh1, bih2, bhh2, b_proj,
                           out, pred, wp);
}

// round 3
// speedup vs baseline: 2.7726x; 2.7726x over previous
#include <cuda_runtime.h>

// ---------------------------------------------------------------------------
// VAE_CDDD_decoder round 3:
//  * All weights repacked as k-packed float4 (LDG.128 streams, prefetch+unroll)
//  * G table (41x768) + W_proj + all hidden state in SMEM (162KB/block)
//  * L1 GRU mapped to 128 threads x 8 rows (no duplicated weight loads)
//  * Double-buffered hidden state -> 4 __syncthreads per step
//  * ONE precompute kernel + main  (2 launches/invocation -> ncu -s5 hits k_main)
// ---------------------------------------------------------------------------

#define BB   1024
#define SS   350
#define VV   41
#define ROWS 8
#define NBLK 128

typedef unsigned long long ull;

// ------------------------- device scratch ----------------------------------
__device__ __align__(16) float4 g_P0 [3 * 64 * 256];  // Whh0 packed [g][k4][t]
__device__ __align__(16) float4 g_P1i[3 * 64 * 128];  // Wih1 packed [g][k4][u]
__device__ __align__(16) float4 g_P1h[3 * 32 * 128];  // Whh1 packed
__device__ __align__(16) float4 g_P2i[3 * 32 * 32];   // Wih2 packed
__device__ __align__(16) float4 g_P2h[3 * 8 * 32];    // Whh2 packed
__device__ __align__(16) float  g_G  [VV * 768];      // fused emb->gi table
__device__ float g_WprojT[32 * VV];
__device__ float g_hinit [BB * 416];

// ------------------------- helpers -----------------------------------------
__device__ __forceinline__ ull splat2(float w) {
    ull r; asm("mov.b64 %0, {%1, %1};" : "=l"(r) : "f"(w)); return r;
}
__device__ __forceinline__ void fma2(ull& acc, ull a, ull b) {
    asm("fma.rn.f32x2 %0, %1, %2, %0;" : "+l"(acc) : "l"(a), "l"(b));
}
__device__ __forceinline__ float2 unpack2(ull v) {
    float2 f; asm("mov.b64 {%0, %1}, %2;" : "=f"(f.x), "=f"(f.y) : "l"(v)); return f;
}
__device__ __forceinline__ float sigm(float x) { return 1.0f / (1.0f + expf(-x)); }

// accumulate 3 gates x 4 row-pair accumulators for one k
#define GRU3(aX, aY, aZ, wx, wy, wzc, hA, hB) do { \
    ull w2x = splat2(wx), w2y = splat2(wy), w2z = splat2(wzc); \
    fma2(aX[0], w2x, hA.x); fma2(aX[1], w2x, hA.y); fma2(aX[2], w2x, hB.x); fma2(aX[3], w2x, hB.y); \
    fma2(aY[0], w2y, hA.x); fma2(aY[1], w2y, hA.y); fma2(aY[2], w2y, hB.x); fma2(aY[3], w2y, hB.y); \
    fma2(aZ[0], w2z, hA.x); fma2(aZ[1], w2z, hA.y); fma2(aZ[2], w2z, hB.x); fma2(aZ[3], w2z, hB.y); \
} while (0)

// 3 gates x 2 row-pair accumulators (4 rows) for one k
#define GRU3H(aX, aY, aZ, wx, wy, wzc, hA) do { \
    ull w2x = splat2(wx), w2y = splat2(wy), w2z = splat2(wzc); \
    fma2(aX[0], w2x, hA.x); fma2(aX[1], w2x, hA.y); \
    fma2(aY[0], w2y, hA.x); fma2(aY[1], w2y, hA.y); \
    fma2(aZ[0], w2z, hA.x); fma2(aZ[1], w2z, hA.y); \
} while (0)

// ------------------------- single precompute kernel -------------------------
__global__ void k_pre(
    const float* __restrict__ latent, const float* __restrict__ b_init,
    const float* __restrict__ W_init,
    const float* __restrict__ W_emb,  const float* __restrict__ b_emb,
    const float* __restrict__ bih0,
    const float* __restrict__ Wih0,   const float* __restrict__ Whh0,
    const float* __restrict__ Wih1,   const float* __restrict__ Whh1,
    const float* __restrict__ Wih2,   const float* __restrict__ Whh2,
    const float* __restrict__ W_proj)
{
    __shared__ float sh[4 * 512];
    const int b = blockIdx.x, tid = threadIdx.x;

    if (b < 256) {                       // hinit: 4 batch rows per block
        const int b0 = b * 4;
        for (int i = tid; i < 4 * 512; i += 256)
            sh[i] = latent[b0 * 512 + i];
        __syncthreads();
        for (int j = tid; j < 416; j += 256) {
            const float bi = b_init[j];
            float a0 = bi, a1 = bi, a2 = bi, a3 = bi;
            const float* w = W_init + j * 512;
            for (int k = 0; k < 512; k++) {
                float wv = w[k];
                a0 += wv * sh[k];
                a1 += wv * sh[512 + k];
                a2 += wv * sh[1024 + k];
                a3 += wv * sh[1536 + k];
            }
            g_hinit[(b0 + 0) * 416 + j] = a0;
            g_hinit[(b0 + 1) * 416 + j] = a1;
            g_hinit[(b0 + 2) * 416 + j] = a2;
            g_hinit[(b0 + 3) * 416 + j] = a3;
        }
    } else if (b < 297) {                // G table: one vocab row per block
        const int v = b - 256;
        for (int e = tid; e < 512; e += 256)
            sh[e] = W_emb[e * VV + v] + b_emb[e];
        __syncthreads();
        for (int f = tid; f < 768; f += 256) {
            float acc = bih0[f];
            const float* w = Wih0 + f * 512;
            for (int e = 0; e < 512; e++) acc += sh[e] * w[e];
            g_G[v * 768 + f] = acc;
        }
    } else if (b < 489) {                // pack Whh0 -> P0
        int idx = (b - 297) * 256 + tid;              // < 49152
        int t = idx & 255, k4 = (idx >> 8) & 63, g = idx >> 14;
        g_P0[idx] = *(const float4*)(Whh0 + (g * 256 + t) * 256 + k4 * 4);
    } else if (b < 585) {                // pack Wih1 -> P1i
        int idx = (b - 489) * 256 + tid;              // < 24576
        int u = idx & 127, k4 = (idx >> 7) & 63, g = idx >> 13;
        g_P1i[idx] = *(const float4*)(Wih1 + (g * 128 + u) * 256 + k4 * 4);
    } else if (b < 633) {                // pack Whh1 -> P1h
        int idx = (b - 585) * 256 + tid;              // < 12288
        int u = idx & 127, k4 = (idx >> 7) & 31, g = idx >> 12;
        g_P1h[idx] = *(const float4*)(Whh1 + (g * 128 + u) * 128 + k4 * 4);
    } else if (b < 645) {                // pack Wih2 -> P2i
        int idx = (b - 633) * 256 + tid;              // < 3072
        int u = idx & 31, k4 = (idx >> 5) & 31, g = idx >> 10;
        g_P2i[idx] = *(const float4*)(Wih2 + (g * 32 + u) * 128 + k4 * 4);
    } else if (b < 648) {                // pack Whh2 -> P2h
        int idx = (b - 645) * 256 + tid;              // < 768
        int u = idx & 31, k4 = (idx >> 5) & 7, g = idx >> 8;
        g_P2h[idx] = *(const float4*)(Whh2 + (g * 32 + u) * 32 + k4 * 4);
    } else {                             // proj transpose
        for (int idx = tid; idx < 32 * VV; idx += 256) {
            int k = idx / VV, v = idx - k * VV;
            g_WprojT[idx] = W_proj[v * 32 + k];
        }
    }
}

// ------------------------- main persistent kernel ---------------------------
// dyn smem floats: G 31488 | h0 2*2048 | h1 2*1024 | h2 2*256 | proj 1312 |
//                  slog 328 | bproj 41 | + stok bytes 2800
#define SM_FLOATS (31488 + 4096 + 2048 + 512 + 1312 + 328 + 41)
#define SMEM_BYTES (SM_FLOATS * 4 + 2800)

__global__ __launch_bounds__(256, 1) void k_main(
    const int*   __restrict__ target,
    const float* __restrict__ bhh0,
    const float* __restrict__ bih1, const float* __restrict__ bhh1,
    const float* __restrict__ bih2, const float* __restrict__ bhh2,
    const float* __restrict__ bproj,
    float* __restrict__ out, float* __restrict__ pred, int write_pred)
{
    extern __shared__ __align__(16) char smraw[];
    float* Gs    = (float*)smraw;        // 31488
    float* h0b   = Gs    + 31488;        // 2 * 2048
    float* h1b   = h0b   + 4096;         // 2 * 1024
    float* h2b   = h1b   + 2048;         // 2 * 256
    float* projS = h2b   + 512;          // 1312
    float* slog  = projS + 1312;         // 328
    float* bprjS = slog  + 328;          // 41
    unsigned char* stok = (unsigned char*)(bprjS + 41);   // 2800

    const int t    = threadIdx.x;
    const int row0 = blockIdx.x * ROWS;

    // ---- stage G + proj into SMEM ----
    {
        float4* Gd = (float4*)Gs;
        const float4* Gg = (const float4*)g_G;
        for (int i = t; i < 31488 / 4; i += 256) Gd[i] = Gg[i];
    }
    for (int i = t; i < 1312; i += 256) projS[i] = g_WprojT[i];
    if (t < VV) bprjS[t] = bproj[t];

    // ---- initial hidden state into buffer 0 ----
    #pragma unroll
    for (int r = 0; r < ROWS; r++)
        h0b[t * 8 + r] = g_hinit[(row0 + r) * 416 + t];
    if (t < 128) {
        #pragma unroll
        for (int r = 0; r < ROWS; r++)
            h1b[t * 8 + r] = g_hinit[(row0 + r) * 416 + 256 + t];
    }
    if (t < 32) {
        #pragma unroll
        for (int r = 0; r < ROWS; r++)
            h2b[t * 8 + r] = g_hinit[(row0 + r) * 416 + 384 + t];
    }
    // ---- tokens (teacher forcing: tok[0]=SOS, else target[:,s]) ----
    for (int i = t; i < SS * ROWS; i += 256) {
        int s = i >> 3, r = i & 7;
        int tk = (s == 0) ? 1 : target[(row0 + r) * SS + s];
        stok[i] = (unsigned char)tk;
    }

    // ---- biases in registers ----
    const float b0r = bhh0[t], b0z = bhh0[t + 256], b0n = bhh0[t + 512];
    float b1r = 0.f, b1z = 0.f, b1i = 0.f, b1h = 0.f;
    if (t < 128) {
        b1r = bih1[t] + bhh1[t];
        b1z = bih1[t + 128] + bhh1[t + 128];
        b1i = bih1[t + 256];
        b1h = bhh1[t + 256];
    }
    int u2 = t & 31, rb2 = (t >> 5) * 4;
    float b2r = 0.f, b2z = 0.f, b2i = 0.f, b2h = 0.f;
    if (t < 64) {
        b2r = bih2[u2] + bhh2[u2];
        b2z = bih2[u2 + 32] + bhh2[u2 + 32];
        b2i = bih2[u2 + 64];
        b2h = bhh2[u2 + 64];
    }
    __syncthreads();

    int cur = 0;
    for (int step = 0; step < SS; ++step) {
        const int nxt = cur ^ 1;
        const float* h0c = h0b + cur * 2048;
        float*       h0n = h0b + nxt * 2048;
        const float* h1c = h1b + cur * 1024;
        float*       h1n = h1b + nxt * 1024;
        const float* h2c = h2b + cur * 256;
        float*       h2n = h2b + nxt * 256;

        // ================= layer 0 =================
        float gir[8], giz[8], gin[8];
        #pragma unroll
        for (int r = 0; r < ROWS; r++) {
            int base = (int)stok[step * 8 + r] * 768 + t;
            gir[r] = Gs[base]; giz[r] = Gs[base + 256]; gin[r] = Gs[base + 512];
        }
        ull ar[4], az[4], an[4];
        #pragma unroll
        for (int p = 0; p < 4; p++) { ar[p] = splat2(b0r); az[p] = splat2(b0z); an[p] = splat2(b0n); }
        {
            const float4* Pr = g_P0;
            const float4* Pz = g_P0 + 16384;
            const float4* Pn = g_P0 + 32768;
            float4 fwr = __ldg(&Pr[t]), fwz = __ldg(&Pz[t]), fwn = __ldg(&Pn[t]);
            #pragma unroll 4
            for (int k4 = 0; k4 < 64; ++k4) {
                float4 wr = fwr, wz = fwz, wn = fwn;
                if (k4 < 63) {
                    int o = (k4 + 1) * 256 + t;
                    fwr = __ldg(&Pr[o]); fwz = __ldg(&Pz[o]); fwn = __ldg(&Pn[o]);
                }
                const ulonglong2* hp = (const ulonglong2*)(h0c + k4 * 32);
                ulonglong2 hA0 = hp[0], hB0 = hp[1], hA1 = hp[2], hB1 = hp[3];
                ulonglong2 hA2 = hp[4], hB2 = hp[5], hA3 = hp[6], hB3 = hp[7];
                GRU3(ar, az, an, wr.x, wz.x, wn.x, hA0, hB0);
                GRU3(ar, az, an, wr.y, wz.y, wn.y, hA1, hB1);
                GRU3(ar, az, an, wr.z, wz.z, wn.z, hA2, hB2);
                GRU3(ar, az, an, wr.w, wz.w, wn.w, hA3, hB3);
            }
        }
        {
            float h0new[8];
            #pragma unroll
            for (int p = 0; p < 4; p++) {
                float2 fr = unpack2(ar[p]), fz = unpack2(az[p]), fn = unpack2(an[p]);
                int i0 = 2 * p, i1 = i0 + 1;
                float rg = sigm(gir[i0] + fr.x);
                float zg = sigm(giz[i0] + fz.x);
                float ng = tanhf(gin[i0] + rg * fn.x);
                h0new[i0] = (1.0f - zg) * ng + zg * h0c[t * 8 + i0];
                rg = sigm(gir[i1] + fr.y);
                zg = sigm(giz[i1] + fz.y);
                ng = tanhf(gin[i1] + rg * fn.y);
                h0new[i1] = (1.0f - zg) * ng + zg * h0c[t * 8 + i1];
            }
            *(float4*)(h0n + t * 8)     = make_float4(h0new[0], h0new[1], h0new[2], h0new[3]);
            *(float4*)(h0n + t * 8 + 4) = make_float4(h0new[4], h0new[5], h0new[6], h0new[7]);
        }
        __syncthreads();                                   // S1

        // ================= layer 1 (threads 0..127, unit=t, 8 rows) ========
        if (t < 128) {
            ull a1r[4], a1z[4], a1i[4], a1h[4];
            #pragma unroll
            for (int p = 0; p < 4; p++) {
                a1r[p] = splat2(b1r); a1z[p] = splat2(b1z);
                a1i[p] = splat2(b1i); a1h[p] = splat2(b1h);
            }
            {   // gi side: k over 256 (h0 new)
                const float4* Qr = g_P1i;
                const float4* Qz = g_P1i + 8192;
                const float4* Qn = g_P1i + 16384;
                float4 fwr = __ldg(&Qr[t]), fwz = __ldg(&Qz[t]), fwn = __ldg(&Qn[t]);
                #pragma unroll 4
                for (int k4 = 0; k4 < 64; ++k4) {
                    float4 wr = fwr, wz = fwz, wn = fwn;
                    if (k4 < 63) {
                        int o = (k4 + 1) * 128 + t;
                        fwr = __ldg(&Qr[o]); fwz = __ldg(&Qz[o]); fwn = __ldg(&Qn[o]);
                    }
                    const ulonglong2* hp = (const ulonglong2*)(h0n + k4 * 32);
                    ulonglong2 hA0 = hp[0], hB0 = hp[1], hA1 = hp[2], hB1 = hp[3];
                    ulonglong2 hA2 = hp[4], hB2 = hp[5], hA3 = hp[6], hB3 = hp[7];
                    GRU3(a1r, a1z, a1i, wr.x, wz.x, wn.x, hA0, hB0);
                    GRU3(a1r, a1z, a1i, wr.y, wz.y, wn.y, hA1, hB1);
                    GRU3(a1r, a1z, a1i, wr.z, wz.z, wn.z, hA2, hB2);
                    GRU3(a1r, a1z, a1i, wr.w, wz.w, wn.w, hA3, hB3);
                }
            }
            {   // gh side: k over 128 (h1 old)
                const float4* Rr = g_P1h;
                const float4* Rz = g_P1h + 4096;
                const float4* Rn = g_P1h + 8192;
                float4 fwr = __ldg(&Rr[t]), fwz = __ldg(&Rz[t]), fwn = __ldg(&Rn[t]);
                #pragma unroll 4
                for (int k4 = 0; k4 < 32; ++k4) {
                    float4 wr = fwr, wz = fwz, wn = fwn;
                    if (k4 < 31) {
                        int o = (k4 + 1) * 128 + t;
                        fwr = __ldg(&Rr[o]); fwz = __ldg(&Rz[o]); fwn = __ldg(&Rn[o]);
                    }
                    const ulonglong2* hp = (const ulonglong2*)(h1c + k4 * 32);
                    ulonglong2 hA0 = hp[0], hB0 = hp[1], hA1 = hp[2], hB1 = hp[3];
                    ulonglong2 hA2 = hp[4], hB2 = hp[5], hA3 = hp[6], hB3 = hp[7];
                    GRU3(a1r, a1z, a1h, wr.x, wz.x, wn.x, hA0, hB0);
                    GRU3(a1r, a1z, a1h, wr.y, wz.y, wn.y, hA1, hB1);
                    GRU3(a1r, a1z, a1h, wr.z, wz.z, wn.z, hA2, hB2);
                    GRU3(a1r, a1z, a1h, wr.w, wz.w, wn.w, hA3, hB3);
                }
            }
            float h1new[8];
            #pragma unroll
            for (int p = 0; p < 4; p++) {
                float2 fr = unpack2(a1r[p]), fz = unpack2(a1z[p]);
                float2 fi = unpack2(a1i[p]), fh = unpack2(a1h[p]);
                int i0 = 2 * p, i1 = i0 + 1;
                float rg = sigm(fr.x), zg = sigm(fz.x);
                float ng = tanhf(fi.x + rg * fh.x);
                h1new[i0] = (1.0f - zg) * ng + zg * h1c[t * 8 + i0];
                rg = sigm(fr.y); zg = sigm(fz.y);
                ng = tanhf(fi.y + rg * fh.y);
                h1new[i1] = (1.0f - zg) * ng + zg * h1c[t * 8 + i1];
            }
            *(float4*)(h1n + t * 8)     = make_float4(h1new[0], h1new[1], h1new[2], h1new[3]);
            *(float4*)(h1n + t * 8 + 4) = make_float4(h1new[4], h1new[5], h1new[6], h1new[7]);
        }
        __syncthreads();                                   // S2

        // ================= layer 2 (threads 0..63, unit=t&31, 4 rows) ======
        if (t < 64) {
            ull a2r[2], a2z[2], a2i[2], a2h[2];
            a2r[0] = a2r[1] = splat2(b2r);
            a2z[0] = a2z[1] = splat2(b2z);
            a2i[0] = a2i[1] = splat2(b2i);
            a2h[0] = a2h[1] = splat2(b2h);
            {   // gi side: k over 128 (h1 new)
                const float4* Qr = g_P2i;
                const float4* Qz = g_P2i + 1024;
                const float4* Qn = g_P2i + 2048;
                float4 fwr = __ldg(&Qr[u2]), fwz = __ldg(&Qz[u2]), fwn = __ldg(&Qn[u2]);
                #pragma unroll 4
                for (int k4 = 0; k4 < 32; ++k4) {
                    float4 wr = fwr, wz = fwz, wn = fwn;
                    if (k4 < 31) {
                        int o = (k4 + 1) * 32 + u2;
                        fwr = __ldg(&Qr[o]); fwz = __ldg(&Qz[o]); fwn = __ldg(&Qn[o]);
                    }
                    ulonglong2 hA0 = *(const ulonglong2*)(h1n + (k4 * 4 + 0) * 8 + rb2);
                    ulonglong2 hA1 = *(const ulonglong2*)(h1n + (k4 * 4 + 1) * 8 + rb2);
                    ulonglong2 hA2 = *(const ulonglong2*)(h1n + (k4 * 4 + 2) * 8 + rb2);
                    ulonglong2 hA3 = *(const ulonglong2*)(h1n + (k4 * 4 + 3) * 8 + rb2);
                    GRU3H(a2r, a2z, a2i, wr.x, wz.x, wn.x, hA0);
                    GRU3H(a2r, a2z, a2i, wr.y, wz.y, wn.y, hA1);
                    GRU3H(a2r, a2z, a2i, wr.z, wz.z, wn.z, hA2);
                    GRU3H(a2r, a2z, a2i, wr.w, wz.w, wn.w, hA3);
                }
            }
            {   // gh side: k over 32 (h2 old)
                const float4* Rr = g_P2h;
                const float4* Rz = g_P2h + 256;
                const float4* Rn = g_P2h + 512;
                float4 fwr = __ldg(&Rr[u2]), fwz = __ldg(&Rz[u2]), fwn = __ldg(&Rn[u2]);
                #pragma unroll
                for (int k4 = 0; k4 < 8; ++k4) {
                    float4 wr = fwr, wz = fwz, wn = fwn;
                    if (k4 < 7) {
                        int o = (k4 + 1) * 32 + u2;
                        fwr = __ldg(&Rr[o]); fwz = __ldg(&Rz[o]); fwn = __ldg(&Rn[o]);
                    }
                    ulonglong2 hA0 = *(const ulonglong2*)(h2c + (k4 * 4 + 0) * 8 + rb2);
                    ulonglong2 hA1 = *(const ulonglong2*)(h2c + (k4 * 4 + 1) * 8 + rb2);
                    ulonglong2 hA2 = *(const ulonglong2*)(h2c + (k4 * 4 + 2) * 8 + rb2);
                    ulonglong2 hA3 = *(const ulonglong2*)(h2c + (k4 * 4 + 3) * 8 + rb2);
                    GRU3H(a2r, a2z, a2h, wr.x, wz.x, wn.x, hA0);
                    GRU3H(a2r, a2z, a2h, wr.y, wz.y, wn.y, hA1);
                    GRU3H(a2r, a2z, a2h, wr.z, wz.z, wn.z, hA2);
                    GRU3H(a2r, a2z, a2h, wr.w, wz.w, wn.w, hA3);
                }
            }
            float h2new[4];
            #pragma unroll
            for (int p = 0; p < 2; p++) {
                float2 fr = unpack2(a2r[p]), fz = unpack2(a2z[p]);
                float2 fi = unpack2(a2i[p]), fh = unpack2(a2h[p]);
                int j0 = 2 * p, j1 = j0 + 1;
                float rg = sigm(fr.x), zg = sigm(fz.x);
                float ng = tanhf(fi.x + rg * fh.x);
                h2new[j0] = (1.0f - zg) * ng + zg * h2c[u2 * 8 + rb2 + j0];
                rg = sigm(fr.y); zg = sigm(fz.y);
                ng = tanhf(fi.y + rg * fh.y);
                h2new[j1] = (1.0f - zg) * ng + zg * h2c[u2 * 8 + rb2 + j1];
            }
            *(float4*)(h2n + u2 * 8 + rb2) = make_float4(h2new[0], h2new[1], h2new[2], h2new[3]);
        }
        __syncthreads();                                   // S3

        // ================= projection + argmax =============================
        for (int idx = t; idx < VV * ROWS; idx += 256) {
            int r = idx / VV, v = idx - r * VV;
            float acc = bprjS[v];
            #pragma unroll
            for (int k = 0; k < 32; k++)
                acc += h2n[k * 8 + r] * projS[k * VV + v];
            out[((size_t)(row0 + r) * SS + step) * VV + v] = acc;
            slog[v * 8 + r] = acc;
        }
        __syncthreads();                                   // S4
        if (t < ROWS && write_pred) {
            float best = slog[t]; int bi = 0;
            #pragma unroll
            for (int v = 1; v < VV; v++) {
                float x = slog[v * 8 + t];
                if (x > best) { best = x; bi = v; }
            }
            pred[(size_t)(row0 + t) * SS + step] = (float)bi;
        }
        cur = nxt;
    }
}

// ------------------------- launch ------------------------------------------
extern "C" void kernel_launch(void* const* d_in, const int* in_sizes, int n_in,
                              void* d_out, int out_size) {
    const float* latent = (const float*)d_in[0];
    const int*   target = (const int*)  d_in[1];
    const float* W_emb  = (const float*)d_in[2];
    const float* b_emb  = (const float*)d_in[3];
    const float* W_init = (const float*)d_in[4];
    const float* b_init = (const float*)d_in[5];
    const float* Wih0   = (const float*)d_in[6];
    const float* Whh0   = (const float*)d_in[7];
    const float* bih0   = (const float*)d_in[8];
    const float* bhh0   = (const float*)d_in[9];
    const float* Wih1   = (const float*)d_in[10];
    const float* Whh1   = (const float*)d_in[11];
    const float* bih1   = (const float*)d_in[12];
    const float* bhh1   = (const float*)d_in[13];
    const float* Wih2   = (const float*)d_in[14];
    const float* Whh2   = (const float*)d_in[15];
    const float* bih2   = (const float*)d_in[16];
    const float* bhh2   = (const float*)d_in[17];
    const float* W_proj = (const float*)d_in[18];
    const float* b_proj = (const float*)d_in[19];
    (void)in_sizes; (void)n_in;

    k_pre<<<649, 256>>>(latent, b_init, W_init, W_emb, b_emb, bih0,
                        Wih0, Whh0, Wih1, Whh1, Wih2, Whh2, W_proj);

    cudaFuncSetAttribute(k_main, cudaFuncAttributeMaxDynamicSharedMemorySize,
                         SMEM_BYTES);

    float* out  = (float*)d_out;
    float* pred = out + (size_t)BB * SS * VV;
    int wp = (out_size >= (int)((size_t)BB * SS * VV + (size_t)BB * SS)) ? 1 : 0;

    k_main<<<NBLK, 256, SMEM_BYTES>>>(target, bhh0, bih1, bhh1, bih2, bhh2,
                                      b_proj, out, pred, wp);
}